// round 15
// baseline (speedup 1.0000x reference)
#include <cuda_runtime.h>
#include <cuda_bf16.h>
#include <math.h>

#define NN 10000
#define EE 160000
#define HH 4
#define NB 31

// ---------------- device scratch (static, no allocation) ----------------
__device__ float d_C[(size_t)NN * 1024]; // per-node: h(256) | Q1(256) | Q2(256) | Q3(256)
__device__ float d_M[12 * 64 * 64];      // M_m[h] = A_top @ F_part
__device__ float d_T[12 * 32 * 64];      // T_m[h][idx][d]
__device__ float d_sc[(size_t)EE * HH];  // attention logits, CSR order
__device__ int   d_deg[NN + 1];
__device__ int   d_off[NN + 1];
__device__ int   d_cur[NN];
__device__ int   d_pos[EE];              // edge -> CSR position
__device__ int   d_srcs[EE];             // CSR-ordered src node ids

// ---------------- helpers ----------------
// overflow-safe tanh without clamp: e^inf -> inf -> 2/inf = 0 -> 1; e^-inf -> 0 -> -1
__device__ __forceinline__ float fast_tanh(float x) {
    float t = __expf(2.f * x);
    return 1.f - __fdividef(2.f, t + 1.f);
}

__device__ __forceinline__ int bucket(float x, const float* __restrict__ b) {
    // #{ i : b[i] < x }, b monotone increasing (~0.1..3.1 step 0.1), exact vs searchsorted
    int i = (int)ceilf((x - 0.1f) * 10.f);
    i = max(0, min(31, i));
    while (i > 0 && __ldg(b + i - 1) >= x) --i;
    while (i < 31 && __ldg(b + i) < x) ++i;
    return i;
}

// ---------------- CSR build ----------------
__global__ void zero_deg_kernel() {
    int i = blockIdx.x * blockDim.x + threadIdx.x;
    if (i <= NN) d_deg[i] = 0;
}

__global__ void hist_kernel(const int* __restrict__ dst) {
    int e = blockIdx.x * blockDim.x + threadIdx.x;
    if (e < EE) atomicAdd(&d_deg[dst[e]], 1);
}

// single block, 1024 threads, 10 elements/thread, warp-shfl block scan
__global__ void scan_kernel() {
    __shared__ int warpsum[32];
    int tid = threadIdx.x;
    int lane = tid & 31, wid = tid >> 5;
    int base = tid * 10;
    int loc[10];
    int s = 0;
    #pragma unroll
    for (int j = 0; j < 10; ++j) {
        int idx = base + j;
        int v = (idx < NN) ? d_deg[idx] : 0;
        loc[j] = s;
        s += v;
    }
    int x = s;
    #pragma unroll
    for (int off = 1; off < 32; off <<= 1) {
        int y = __shfl_up_sync(0xffffffffu, x, off);
        if (lane >= off) x += y;
    }
    if (lane == 31) warpsum[wid] = x;
    __syncthreads();
    if (wid == 0) {
        int t = warpsum[lane];
        #pragma unroll
        for (int off = 1; off < 32; off <<= 1) {
            int y = __shfl_up_sync(0xffffffffu, t, off);
            if (lane >= off) t += y;
        }
        warpsum[lane] = t;
    }
    __syncthreads();
    int warpbase = (wid > 0) ? warpsum[wid - 1] : 0;
    int excl = warpbase + x - s;
    #pragma unroll
    for (int j = 0; j < 10; ++j) {
        int idx = base + j;
        if (idx < NN) { d_off[idx] = excl + loc[j]; d_cur[idx] = excl + loc[j]; }
    }
    if (tid == 0) d_off[NN] = warpsum[31];
}

__global__ void scatter_kernel(const int* __restrict__ dst, const int* __restrict__ src) {
    int e = blockIdx.x * blockDim.x + threadIdx.x;
    if (e < EE) {
        int p = atomicAdd(&d_cur[dst[e]], 1);
        d_pos[e] = p;
        d_srcs[p] = src[e];
    }
}

// ---------------- smem matmul helpers (trailing sync) ----------------
__device__ __forceinline__ void mm64(float* __restrict__ o, const float* __restrict__ a,
                                     const float* __restrict__ b, int tid) {
    int ty = tid >> 4, tx = tid & 15;
    int r0 = ty * 4, c0 = tx * 4;
    float acc[4][4] = {};
    for (int k = 0; k < 64; ++k) {
        float av[4];
        #pragma unroll
        for (int i = 0; i < 4; ++i) av[i] = a[(r0 + i) * 64 + k];
        const float* bp = b + k * 64 + c0;
        float b0 = bp[0], b1 = bp[1], b2 = bp[2], b3 = bp[3];
        #pragma unroll
        for (int i = 0; i < 4; ++i) {
            acc[i][0] += av[i] * b0; acc[i][1] += av[i] * b1;
            acc[i][2] += av[i] * b2; acc[i][3] += av[i] * b3;
        }
    }
    #pragma unroll
    for (int i = 0; i < 4; ++i)
        #pragma unroll
        for (int j = 0; j < 4; ++j) o[(r0 + i) * 64 + c0 + j] = acc[i][j];
    __syncthreads();
}

__device__ __forceinline__ void mm32_64(float* __restrict__ o, const float* __restrict__ a,
                                        const float* __restrict__ b, int tid) {
    int ty = tid >> 4, tx = tid & 15;
    int r0 = ty * 2, c0 = tx * 4;
    float acc[2][4] = {};
    for (int k = 0; k < 64; ++k) {
        float a0 = a[r0 * 64 + k], a1 = a[(r0 + 1) * 64 + k];
        const float* bp = b + k * 64 + c0;
        float b0 = bp[0], b1 = bp[1], b2 = bp[2], b3 = bp[3];
        acc[0][0] += a0 * b0; acc[0][1] += a0 * b1; acc[0][2] += a0 * b2; acc[0][3] += a0 * b3;
        acc[1][0] += a1 * b0; acc[1][1] += a1 * b1; acc[1][2] += a1 * b2; acc[1][3] += a1 * b3;
    }
    #pragma unroll
    for (int i = 0; i < 2; ++i)
        #pragma unroll
        for (int j = 0; j < 4; ++j) o[(r0 + i) * 64 + c0 + j] = acc[i][j];
    __syncthreads();
}

// ---------------- prep: T tables + M matrices (12 blocks = m*4+h) ----------------
__global__ void prep_kernel(const float* __restrict__ fc1, const float* __restrict__ fc2,
                            const float* __restrict__ fc3, const float* __restrict__ fcF,
                            const float* __restrict__ G, const float* __restrict__ emb) {
    __shared__ float sX[4096];
    __shared__ float sY[4096];
    __shared__ float sZ[4096];
    int bx = blockIdx.x;
    int m = bx / HH, h = bx % HH;
    int tid = threadIdx.x;
    const float* Aw = (m == 0 ? fc1 : (m == 1 ? fc2 : fc3)) + (size_t)h * 128 * 64;
    const float* F  = fcF + (size_t)h * 192 * 64 + (size_t)m * 64 * 64;

    for (int o = tid; o < 4096; o += 256) { sY[o] = F[o]; sX[o] = Aw[4096 + o]; }
    __syncthreads();
    mm64(sZ, sX, sY, tid);                     // Z = A_bot @ F
    const float* Gh = G + (size_t)h * 2048;
    for (int o = tid; o < 2048; o += 256) sX[o] = Gh[o];
    __syncthreads();
    mm32_64(sX + 2048, sX, sZ, tid);           // GA = G @ AF
    for (int o = tid; o < 1024; o += 256) sZ[o] = emb[o];
    __syncthreads();
    {   // T = emb @ GA -> d_T
        int ty = tid >> 4, tx = tid & 15;
        int r0 = ty * 2, c0 = tx * 4;
        float acc[2][4] = {};
        for (int k = 0; k < 32; ++k) {
            float a0 = sZ[r0 * 32 + k], a1 = sZ[(r0 + 1) * 32 + k];
            const float* bp = sX + 2048 + k * 64 + c0;
            float b0 = bp[0], b1 = bp[1], b2 = bp[2], b3 = bp[3];
            acc[0][0] += a0 * b0; acc[0][1] += a0 * b1; acc[0][2] += a0 * b2; acc[0][3] += a0 * b3;
            acc[1][0] += a1 * b0; acc[1][1] += a1 * b1; acc[1][2] += a1 * b2; acc[1][3] += a1 * b3;
        }
        #pragma unroll
        for (int i = 0; i < 2; ++i)
            #pragma unroll
            for (int j = 0; j < 4; ++j)
                d_T[bx * 2048 + (r0 + i) * 64 + c0 + j] = acc[i][j];
    }
    __syncthreads();
    for (int o = tid; o < 4096; o += 256) sX[o] = Aw[o];
    __syncthreads();
    mm64(sZ, sX, sY, tid);                     // M = A_top @ F
    for (int o = tid; o < 4096; o += 256) d_M[bx * 4096 + o] = sZ[o];
}

// ---------------- stage-1 GEMM: C[:,0..255] = feat[N,128] @ wfc[128,256] ----------------
__global__ void __launch_bounds__(256, 2) gemm1_kernel(const float* __restrict__ A,
                                                       const float* __restrict__ W) {
    __shared__ float As[16][128];
    __shared__ float Bs[16][128];
    int bx = blockIdx.x;   // 2 column tiles of 128
    int by = blockIdx.y;
    int tid = threadIdx.x;
    int tx = tid & 15, ty = tid >> 4;
    float acc[8][8] = {};
    int rowBase = by * 128;
    for (int k0 = 0; k0 < 128; k0 += 16) {
        {
            int r = tid >> 1;
            int c = (tid & 1) * 8;
            int row = rowBase + r;
            float4 v0, v1;
            if (row < NN) {
                v0 = *(const float4*)(A + (size_t)row * 128 + k0 + c);
                v1 = *(const float4*)(A + (size_t)row * 128 + k0 + c + 4);
            } else {
                v0 = make_float4(0.f, 0.f, 0.f, 0.f);
                v1 = v0;
            }
            As[c + 0][r] = v0.x; As[c + 1][r] = v0.y; As[c + 2][r] = v0.z; As[c + 3][r] = v0.w;
            As[c + 4][r] = v1.x; As[c + 5][r] = v1.y; As[c + 6][r] = v1.z; As[c + 7][r] = v1.w;
        }
        {
            int i = tid * 8;
            int r = i >> 7, c = i & 127;
            const float* srcp = W + (size_t)(k0 + r) * 256 + bx * 128 + c;
            *(float4*)(&Bs[r][c])     = *(const float4*)(srcp);
            *(float4*)(&Bs[r][c + 4]) = *(const float4*)(srcp + 4);
        }
        __syncthreads();
        #pragma unroll
        for (int k = 0; k < 16; ++k) {
            float a[8], b[8];
            *(float4*)(a)     = *(const float4*)(&As[k][ty * 8]);
            *(float4*)(a + 4) = *(const float4*)(&As[k][ty * 8 + 4]);
            *(float4*)(b)     = *(const float4*)(&Bs[k][tx * 8]);
            *(float4*)(b + 4) = *(const float4*)(&Bs[k][tx * 8 + 4]);
            #pragma unroll
            for (int i = 0; i < 8; ++i)
                #pragma unroll
                for (int j = 0; j < 8; ++j) acc[i][j] += a[i] * b[j];
        }
        __syncthreads();
    }
    #pragma unroll
    for (int i = 0; i < 8; ++i) {
        int row = rowBase + ty * 8 + i;
        if (row < NN) {
            float* dstp = d_C + (size_t)row * 1024 + bx * 128 + tx * 8;
            *(float4*)(dstp)     = make_float4(acc[i][0], acc[i][1], acc[i][2], acc[i][3]);
            *(float4*)(dstp + 4) = make_float4(acc[i][4], acc[i][5], acc[i][6], acc[i][7]);
        }
    }
}

// ---------------- stage-2: all 3 m-projections per block, conflict-free smem ---------
#define HST 65
__global__ void __launch_bounds__(256, 3) gemm2_kernel() {
    extern __shared__ float smem[];
    float* sM = smem;              // 3 * 4096
    float* sH = smem + 3 * 4096;   // 64 * HST
    int h = blockIdx.y;
    int rowBase = blockIdx.x * 64;
    int tid = threadIdx.x;
    int ty = tid >> 4, tx = tid & 15;

    #pragma unroll
    for (int m = 0; m < 3; ++m) {
        const float* srcp = d_M + (m * HH + h) * 4096;
        for (int o = tid * 4; o < 4096; o += 1024)
            *(float4*)(sM + m * 4096 + o) = *(const float4*)(srcp + o);
    }
    {
        int r = tid >> 2;
        int seg = (tid & 3) * 16;
        int row = rowBase + r;
        float* dstp = sH + r * HST + seg;
        if (row < NN) {
            const float* srcp = d_C + (size_t)row * 1024 + h * 64 + seg;
            #pragma unroll
            for (int q = 0; q < 4; ++q) {
                float4 v = *(const float4*)(srcp + q * 4);
                dstp[q * 4 + 0] = v.x; dstp[q * 4 + 1] = v.y;
                dstp[q * 4 + 2] = v.z; dstp[q * 4 + 3] = v.w;
            }
        } else {
            #pragma unroll
            for (int q = 0; q < 16; ++q) dstp[q] = 0.f;
        }
    }
    __syncthreads();

    float acc[3][4][4] = {};
    int c0 = tx * 4;
    const float* sB0 = sM + c0;
    #pragma unroll 4
    for (int k = 0; k < 64; ++k) {
        float a[4];
        #pragma unroll
        for (int i = 0; i < 4; ++i) a[i] = sH[(ty + 16 * i) * HST + k];
        #pragma unroll
        for (int m = 0; m < 3; ++m) {
            float4 bv = *(const float4*)(sB0 + m * 4096 + k * 64);
            #pragma unroll
            for (int i = 0; i < 4; ++i) {
                acc[m][i][0] += a[i] * bv.x; acc[m][i][1] += a[i] * bv.y;
                acc[m][i][2] += a[i] * bv.z; acc[m][i][3] += a[i] * bv.w;
            }
        }
    }
    #pragma unroll
    for (int m = 0; m < 3; ++m)
        #pragma unroll
        for (int i = 0; i < 4; ++i) {
            int row = rowBase + ty + 16 * i;
            if (row < NN)
                *(float4*)(d_C + (size_t)row * 1024 + 256 + m * 256 + h * 64 + c0) =
                    make_float4(acc[m][i][0], acc[m][i][1], acc[m][i][2], acc[m][i][3]);
        }
}
#define G2_SMEM ((3 * 4096 + 64 * HST) * (int)sizeof(float))

// ---------------- score kernel: TWO EDGES PER WARP (16 lanes x float4 each) ----------
// lanes 0-15: edge eA; lanes 16-31: edge eB. Each lane covers 4 of 64 dims.
__global__ void score_kernel(const float* __restrict__ pos, const int* __restrict__ srcA,
                             const int* __restrict__ dstA, const int* __restrict__ interA,
                             const float* __restrict__ ao, const float* __restrict__ bnds) {
    int gw = (blockIdx.x * blockDim.x + threadIdx.x) >> 5;  // warp id
    int lane = threadIdx.x & 31;
    int half = lane >> 4;        // 0 or 1
    int hl = lane & 15;          // lane within half
    int e = gw * 2 + half;
    if (e >= EE) return;

    int s = __ldg(srcA + e);
    int v = __ldg(dstA + e);
    int4 itv = __ldg((const int4*)interA + e);

    // --- parallel distance + bucket: hl 0..8 handles pair j for this half's edge ---
    // j=0: (v,s); j=1..4: (v,it[j-1]); j=5..8: (s,it[j-5])
    int j = min(hl, 8);
    int aid = (j >= 5) ? s : v;
    int k = (j >= 5) ? (j - 5) : (j - 1);
    int bid = s;
    if (j >= 1) {
        bid = (k == 0) ? itv.x : ((k == 1) ? itv.y : ((k == 2) ? itv.z : itv.w));
    }
    float ax = __ldg(pos + (size_t)aid * 3 + 0);
    float ay = __ldg(pos + (size_t)aid * 3 + 1);
    float az = __ldg(pos + (size_t)aid * 3 + 2);
    float bxp = __ldg(pos + (size_t)bid * 3 + 0);
    float byp = __ldg(pos + (size_t)bid * 3 + 1);
    float bzp = __ldg(pos + (size_t)bid * 3 + 2);
    float dd = sqrtf((ax - bxp) * (ax - bxp) + (ay - byp) * (ay - byp) + (az - bzp) * (az - bzp));
    int bkt = bucket(dd, bnds);

    int sb = half << 4;  // shfl source base for this half
    int i1   = __shfl_sync(0xffffffffu, bkt, sb + 0);
    int i2_0 = __shfl_sync(0xffffffffu, bkt, sb + 1);
    int i2_1 = __shfl_sync(0xffffffffu, bkt, sb + 2);
    int i2_2 = __shfl_sync(0xffffffffu, bkt, sb + 3);
    int i2_3 = __shfl_sync(0xffffffffu, bkt, sb + 4);
    int i3_0 = __shfl_sync(0xffffffffu, bkt, sb + 5);
    int i3_1 = __shfl_sync(0xffffffffu, bkt, sb + 6);
    int i3_2 = __shfl_sync(0xffffffffu, bkt, sb + 7);
    int i3_3 = __shfl_sync(0xffffffffu, bkt, sb + 8);

    const float* Cs = d_C + (size_t)s * 1024;
    const float* Cv = d_C + (size_t)v * 1024;

    float acc0, acc1, acc2, acc3;
    #define HEAD_SCORE(h, ITN, I2, I3, ACC) {                                               \
        const float* Ci = d_C + (size_t)(ITN) * 1024;                                        \
        float4 q1 = __ldg((const float4*)(Cs + 256 + (h) * 64) + hl);                        \
        float4 q2 = __ldg((const float4*)(Ci + 512 + (h) * 64) + hl);                        \
        float4 q3 = __ldg((const float4*)(Cv + 768 + (h) * 64) + hl);                        \
        float4 t1 = __ldg((const float4*)(d_T + ((0 * HH + (h)) * 32 + i1) * 64) + hl);      \
        float4 t2 = __ldg((const float4*)(d_T + ((1 * HH + (h)) * 32 + (I2)) * 64) + hl);    \
        float4 t3 = __ldg((const float4*)(d_T + ((2 * HH + (h)) * 32 + (I3)) * 64) + hl);    \
        float4 av = __ldg((const float4*)(ao + (h) * 64) + hl);                              \
        float z0 = q1.x + q2.x + q3.x + t1.x + t2.x + t3.x;                                  \
        float z1 = q1.y + q2.y + q3.y + t1.y + t2.y + t3.y;                                  \
        float z2 = q1.z + q2.z + q3.z + t1.z + t2.z + t3.z;                                  \
        float z3 = q1.w + q2.w + q3.w + t1.w + t2.w + t3.w;                                  \
        ACC = fast_tanh(z0) * av.x + fast_tanh(z1) * av.y                                    \
            + fast_tanh(z2) * av.z + fast_tanh(z3) * av.w;                                   \
    }
    HEAD_SCORE(0, itv.x, i2_0, i3_0, acc0)
    HEAD_SCORE(1, itv.y, i2_1, i3_1, acc1)
    HEAD_SCORE(2, itv.z, i2_2, i3_2, acc2)
    HEAD_SCORE(3, itv.w, i2_3, i3_3, acc3)
    #undef HEAD_SCORE

    // butterfly within each 16-lane half
    #pragma unroll
    for (int o = 8; o > 0; o >>= 1) {
        acc0 += __shfl_xor_sync(0xffffffffu, acc0, o);
        acc1 += __shfl_xor_sync(0xffffffffu, acc1, o);
        acc2 += __shfl_xor_sync(0xffffffffu, acc2, o);
        acc3 += __shfl_xor_sync(0xffffffffu, acc3, o);
    }
    if (hl == 0) {
        int p = __ldg(d_pos + e);
        *(float4*)(d_sc + (size_t)p * HH) = make_float4(acc0, acc1, acc2, acc3);
    }
}

// ---------------- aggregation: one block per dst, one warp per head ----------------
__global__ void agg_kernel(float* __restrict__ out) {
    int v = blockIdx.x;
    int tid = threadIdx.x;
    int h = tid >> 5, lane = tid & 31;
    __shared__ float sFT[4][64];

    int beg = d_off[v], end = d_off[v + 1];

    float mx = -3.4e38f, den = 0.f;
    float accx = 0.f, accy = 0.f;

    for (int c = beg; c < end; c += 32) {
        int n = min(32, end - c);
        int sL = 0; float scL = 0.f;
        if (lane < n) {
            sL = d_srcs[c + lane];
            scL = d_sc[(size_t)(c + lane) * HH + h];
        }
        for (int jj = 0; jj < n; ++jj) {
            int s    = __shfl_sync(0xffffffffu, sL, jj);
            float sc = __shfl_sync(0xffffffffu, scL, jj);
            float2 hs = ((const float2*)(d_C + (size_t)s * 1024 + h * 64))[lane];
            float nm = fmaxf(mx, sc);
            float scale = __expf(mx - nm);
            float w = __expf(sc - nm);
            den  = den  * scale + w;
            accx = accx * scale + w * hs.x;
            accy = accy * scale + w * hs.y;
            mx = nm;
        }
    }

    float inv = (den > 0.f) ? 1.0f / den : 0.f;
    sFT[h][lane * 2 + 0] = accx * inv;
    sFT[h][lane * 2 + 1] = accy * inv;
    __syncthreads();
    if (tid < 64)
        out[(size_t)v * 64 + tid] = 0.25f * (sFT[0][tid] + sFT[1][tid] + sFT[2][tid] + sFT[3][tid]);
}

// ---------------- launch ----------------
extern "C" void kernel_launch(void* const* d_in, const int* in_sizes, int n_in,
                              void* d_out, int out_size) {
    int i_feat = 0, i_loc = 1, i_src, i_dst, i_inter, i_wfc, i_emb, i_G,
        i_fc1, i_fc2, i_fc3, i_fc, i_ao, i_b;
    if (in_sizes[2] == EE) { // dict order
        i_src = 2; i_dst = 3; i_inter = 4; i_wfc = 5; i_emb = 6; i_G = 7;
        i_fc1 = 8; i_fc2 = 9; i_fc3 = 10; i_fc = 11; i_ao = 12; i_b = 13;
    } else {                 // signature order
        i_wfc = 2; i_emb = 3; i_G = 4; i_fc1 = 5; i_fc2 = 6; i_fc3 = 7;
        i_fc = 8; i_ao = 9; i_b = 10; i_src = 11; i_dst = 12; i_inter = 13;
    }

    const float* feat  = (const float*)d_in[i_feat];
    const float* pos   = (const float*)d_in[i_loc];
    const int*   src   = (const int*)  d_in[i_src];
    const int*   dst   = (const int*)  d_in[i_dst];
    const int*   inter = (const int*)  d_in[i_inter];
    const float* wfc   = (const float*)d_in[i_wfc];
    const float* emb   = (const float*)d_in[i_emb];
    const float* G     = (const float*)d_in[i_G];
    const float* fc1   = (const float*)d_in[i_fc1];
    const float* fc2   = (const float*)d_in[i_fc2];
    const float* fc3   = (const float*)d_in[i_fc3];
    const float* fcF   = (const float*)d_in[i_fc];
    const float* ao    = (const float*)d_in[i_ao];
    const float* bnds  = (const float*)d_in[i_b];
    float* out = (float*)d_out;

    cudaFuncSetAttribute(gemm2_kernel, cudaFuncAttributeMaxDynamicSharedMemorySize, G2_SMEM);

    zero_deg_kernel<<<(NN + 256) / 256, 256>>>();
    prep_kernel<<<12, 256>>>(fc1, fc2, fc3, fcF, G, emb);
    gemm1_kernel<<<dim3(2, (NN + 127) / 128), 256>>>(feat, wfc);
    gemm2_kernel<<<dim3((NN + 63) / 64, 4), 256, G2_SMEM>>>();
    hist_kernel<<<(EE + 255) / 256, 256>>>(dst);
    scan_kernel<<<1, 1024>>>();
    scatter_kernel<<<(EE + 255) / 256, 256>>>(dst, src);
    score_kernel<<<(EE / 2 + 7) / 8, 256>>>(pos, src, dst, inter, ao, bnds);
    agg_kernel<<<NN, 128>>>(out);
}

// round 16
// speedup vs baseline: 1.0428x; 1.0428x over previous
#include <cuda_runtime.h>
#include <cuda_bf16.h>
#include <math.h>

#define NN 10000
#define EE 160000
#define HH 4
#define NB 31

// ---------------- device scratch (static, no allocation) ----------------
__device__ float d_C[(size_t)NN * 1024]; // per-node: h(256) | Q1(256) | Q2(256) | Q3(256)
__device__ float d_M[12 * 64 * 64];      // M_m[h] = A_top @ F_part
__device__ float d_T[12 * 32 * 64];      // T_m[h][idx][d]
__device__ float d_sc[(size_t)EE * HH];  // attention logits, EDGE order
__device__ int   d_deg[NN + 1];
__device__ int   d_off[NN + 1];
__device__ int   d_cur[NN];
__device__ int   d_es[EE];               // CSR-ordered edge ids
__device__ int   d_srcs[EE];             // CSR-ordered src node ids

// ---------------- helpers ----------------
// overflow-safe tanh without clamp
__device__ __forceinline__ float fast_tanh(float x) {
    float t = __expf(2.f * x);
    return 1.f - __fdividef(2.f, t + 1.f);
}

__device__ __forceinline__ int bucket(float x, const float* __restrict__ b) {
    int i = (int)ceilf((x - 0.1f) * 10.f);
    i = max(0, min(31, i));
    while (i > 0 && __ldg(b + i - 1) >= x) --i;
    while (i < 31 && __ldg(b + i) < x) ++i;
    return i;
}

// ---------------- CSR build ----------------
__global__ void zero_deg_kernel() {
    int i = blockIdx.x * blockDim.x + threadIdx.x;
    if (i <= NN) d_deg[i] = 0;
}

__global__ void hist_kernel(const int* __restrict__ dst) {
    int e = blockIdx.x * blockDim.x + threadIdx.x;
    if (e < EE) atomicAdd(&d_deg[dst[e]], 1);
}

__global__ void scan_kernel() {
    __shared__ int warpsum[32];
    int tid = threadIdx.x;
    int lane = tid & 31, wid = tid >> 5;
    int base = tid * 10;
    int loc[10];
    int s = 0;
    #pragma unroll
    for (int j = 0; j < 10; ++j) {
        int idx = base + j;
        int v = (idx < NN) ? d_deg[idx] : 0;
        loc[j] = s;
        s += v;
    }
    int x = s;
    #pragma unroll
    for (int off = 1; off < 32; off <<= 1) {
        int y = __shfl_up_sync(0xffffffffu, x, off);
        if (lane >= off) x += y;
    }
    if (lane == 31) warpsum[wid] = x;
    __syncthreads();
    if (wid == 0) {
        int t = warpsum[lane];
        #pragma unroll
        for (int off = 1; off < 32; off <<= 1) {
            int y = __shfl_up_sync(0xffffffffu, t, off);
            if (lane >= off) t += y;
        }
        warpsum[lane] = t;
    }
    __syncthreads();
    int warpbase = (wid > 0) ? warpsum[wid - 1] : 0;
    int excl = warpbase + x - s;
    #pragma unroll
    for (int j = 0; j < 10; ++j) {
        int idx = base + j;
        if (idx < NN) { d_off[idx] = excl + loc[j]; d_cur[idx] = excl + loc[j]; }
    }
    if (tid == 0) d_off[NN] = warpsum[31];
}

__global__ void scatter_kernel(const int* __restrict__ dst, const int* __restrict__ src) {
    int e = blockIdx.x * blockDim.x + threadIdx.x;
    if (e < EE) {
        int p = atomicAdd(&d_cur[dst[e]], 1);
        d_es[p] = e;
        d_srcs[p] = src[e];
    }
}

// ---------------- smem matmul helpers (trailing sync) ----------------
__device__ __forceinline__ void mm64(float* __restrict__ o, const float* __restrict__ a,
                                     const float* __restrict__ b, int tid) {
    int ty = tid >> 4, tx = tid & 15;
    int r0 = ty * 4, c0 = tx * 4;
    float acc[4][4] = {};
    for (int k = 0; k < 64; ++k) {
        float av[4];
        #pragma unroll
        for (int i = 0; i < 4; ++i) av[i] = a[(r0 + i) * 64 + k];
        const float* bp = b + k * 64 + c0;
        float b0 = bp[0], b1 = bp[1], b2 = bp[2], b3 = bp[3];
        #pragma unroll
        for (int i = 0; i < 4; ++i) {
            acc[i][0] += av[i] * b0; acc[i][1] += av[i] * b1;
            acc[i][2] += av[i] * b2; acc[i][3] += av[i] * b3;
        }
    }
    #pragma unroll
    for (int i = 0; i < 4; ++i)
        #pragma unroll
        for (int j = 0; j < 4; ++j) o[(r0 + i) * 64 + c0 + j] = acc[i][j];
    __syncthreads();
}

__device__ __forceinline__ void mm32_64(float* __restrict__ o, const float* __restrict__ a,
                                        const float* __restrict__ b, int tid) {
    int ty = tid >> 4, tx = tid & 15;
    int r0 = ty * 2, c0 = tx * 4;
    float acc[2][4] = {};
    for (int k = 0; k < 64; ++k) {
        float a0 = a[r0 * 64 + k], a1 = a[(r0 + 1) * 64 + k];
        const float* bp = b + k * 64 + c0;
        float b0 = bp[0], b1 = bp[1], b2 = bp[2], b3 = bp[3];
        acc[0][0] += a0 * b0; acc[0][1] += a0 * b1; acc[0][2] += a0 * b2; acc[0][3] += a0 * b3;
        acc[1][0] += a1 * b0; acc[1][1] += a1 * b1; acc[1][2] += a1 * b2; acc[1][3] += a1 * b3;
    }
    #pragma unroll
    for (int i = 0; i < 2; ++i)
        #pragma unroll
        for (int j = 0; j < 4; ++j) o[(r0 + i) * 64 + c0 + j] = acc[i][j];
    __syncthreads();
}

// ---------------- prep: T tables + M matrices (12 blocks = m*4+h) ----------------
__global__ void prep_kernel(const float* __restrict__ fc1, const float* __restrict__ fc2,
                            const float* __restrict__ fc3, const float* __restrict__ fcF,
                            const float* __restrict__ G, const float* __restrict__ emb) {
    __shared__ float sX[4096];
    __shared__ float sY[4096];
    __shared__ float sZ[4096];
    int bx = blockIdx.x;
    int m = bx / HH, h = bx % HH;
    int tid = threadIdx.x;
    const float* Aw = (m == 0 ? fc1 : (m == 1 ? fc2 : fc3)) + (size_t)h * 128 * 64;
    const float* F  = fcF + (size_t)h * 192 * 64 + (size_t)m * 64 * 64;

    for (int o = tid; o < 4096; o += 256) { sY[o] = F[o]; sX[o] = Aw[4096 + o]; }
    __syncthreads();
    mm64(sZ, sX, sY, tid);                     // Z = A_bot @ F
    const float* Gh = G + (size_t)h * 2048;
    for (int o = tid; o < 2048; o += 256) sX[o] = Gh[o];
    __syncthreads();
    mm32_64(sX + 2048, sX, sZ, tid);           // GA = G @ AF
    for (int o = tid; o < 1024; o += 256) sZ[o] = emb[o];
    __syncthreads();
    {   // T = emb @ GA -> d_T
        int ty = tid >> 4, tx = tid & 15;
        int r0 = ty * 2, c0 = tx * 4;
        float acc[2][4] = {};
        for (int k = 0; k < 32; ++k) {
            float a0 = sZ[r0 * 32 + k], a1 = sZ[(r0 + 1) * 32 + k];
            const float* bp = sX + 2048 + k * 64 + c0;
            float b0 = bp[0], b1 = bp[1], b2 = bp[2], b3 = bp[3];
            acc[0][0] += a0 * b0; acc[0][1] += a0 * b1; acc[0][2] += a0 * b2; acc[0][3] += a0 * b3;
            acc[1][0] += a1 * b0; acc[1][1] += a1 * b1; acc[1][2] += a1 * b2; acc[1][3] += a1 * b3;
        }
        #pragma unroll
        for (int i = 0; i < 2; ++i)
            #pragma unroll
            for (int j = 0; j < 4; ++j)
                d_T[bx * 2048 + (r0 + i) * 64 + c0 + j] = acc[i][j];
    }
    __syncthreads();
    for (int o = tid; o < 4096; o += 256) sX[o] = Aw[o];
    __syncthreads();
    mm64(sZ, sX, sY, tid);                     // M = A_top @ F
    for (int o = tid; o < 4096; o += 256) d_M[bx * 4096 + o] = sZ[o];
}

// ---------------- stage-1 GEMM: C[:,0..255] = feat[N,128] @ wfc[128,256] ----------------
__global__ void __launch_bounds__(256, 2) gemm1_kernel(const float* __restrict__ A,
                                                       const float* __restrict__ W) {
    __shared__ float As[16][128];
    __shared__ float Bs[16][128];
    int bx = blockIdx.x;
    int by = blockIdx.y;
    int tid = threadIdx.x;
    int tx = tid & 15, ty = tid >> 4;
    float acc[8][8] = {};
    int rowBase = by * 128;
    for (int k0 = 0; k0 < 128; k0 += 16) {
        {
            int r = tid >> 1;
            int c = (tid & 1) * 8;
            int row = rowBase + r;
            float4 v0, v1;
            if (row < NN) {
                v0 = *(const float4*)(A + (size_t)row * 128 + k0 + c);
                v1 = *(const float4*)(A + (size_t)row * 128 + k0 + c + 4);
            } else {
                v0 = make_float4(0.f, 0.f, 0.f, 0.f);
                v1 = v0;
            }
            As[c + 0][r] = v0.x; As[c + 1][r] = v0.y; As[c + 2][r] = v0.z; As[c + 3][r] = v0.w;
            As[c + 4][r] = v1.x; As[c + 5][r] = v1.y; As[c + 6][r] = v1.z; As[c + 7][r] = v1.w;
        }
        {
            int i = tid * 8;
            int r = i >> 7, c = i & 127;
            const float* srcp = W + (size_t)(k0 + r) * 256 + bx * 128 + c;
            *(float4*)(&Bs[r][c])     = *(const float4*)(srcp);
            *(float4*)(&Bs[r][c + 4]) = *(const float4*)(srcp + 4);
        }
        __syncthreads();
        #pragma unroll
        for (int k = 0; k < 16; ++k) {
            float a[8], b[8];
            *(float4*)(a)     = *(const float4*)(&As[k][ty * 8]);
            *(float4*)(a + 4) = *(const float4*)(&As[k][ty * 8 + 4]);
            *(float4*)(b)     = *(const float4*)(&Bs[k][tx * 8]);
            *(float4*)(b + 4) = *(const float4*)(&Bs[k][tx * 8 + 4]);
            #pragma unroll
            for (int i = 0; i < 8; ++i)
                #pragma unroll
                for (int j = 0; j < 8; ++j) acc[i][j] += a[i] * b[j];
        }
        __syncthreads();
    }
    #pragma unroll
    for (int i = 0; i < 8; ++i) {
        int row = rowBase + ty * 8 + i;
        if (row < NN) {
            float* dstp = d_C + (size_t)row * 1024 + bx * 128 + tx * 8;
            *(float4*)(dstp)     = make_float4(acc[i][0], acc[i][1], acc[i][2], acc[i][3]);
            *(float4*)(dstp + 4) = make_float4(acc[i][4], acc[i][5], acc[i][6], acc[i][7]);
        }
    }
}

// ---------------- stage-2: all 3 m-projections per block, conflict-free smem ---------
#define HST 65
__global__ void __launch_bounds__(256, 3) gemm2_kernel() {
    extern __shared__ float smem[];
    float* sM = smem;              // 3 * 4096
    float* sH = smem + 3 * 4096;   // 64 * HST
    int h = blockIdx.y;
    int rowBase = blockIdx.x * 64;
    int tid = threadIdx.x;
    int ty = tid >> 4, tx = tid & 15;

    #pragma unroll
    for (int m = 0; m < 3; ++m) {
        const float* srcp = d_M + (m * HH + h) * 4096;
        for (int o = tid * 4; o < 4096; o += 1024)
            *(float4*)(sM + m * 4096 + o) = *(const float4*)(srcp + o);
    }
    {
        int r = tid >> 2;
        int seg = (tid & 3) * 16;
        int row = rowBase + r;
        float* dstp = sH + r * HST + seg;
        if (row < NN) {
            const float* srcp = d_C + (size_t)row * 1024 + h * 64 + seg;
            #pragma unroll
            for (int q = 0; q < 4; ++q) {
                float4 v = *(const float4*)(srcp + q * 4);
                dstp[q * 4 + 0] = v.x; dstp[q * 4 + 1] = v.y;
                dstp[q * 4 + 2] = v.z; dstp[q * 4 + 3] = v.w;
            }
        } else {
            #pragma unroll
            for (int q = 0; q < 16; ++q) dstp[q] = 0.f;
        }
    }
    __syncthreads();

    float acc[3][4][4] = {};
    int c0 = tx * 4;
    const float* sB0 = sM + c0;
    #pragma unroll 4
    for (int k = 0; k < 64; ++k) {
        float a[4];
        #pragma unroll
        for (int i = 0; i < 4; ++i) a[i] = sH[(ty + 16 * i) * HST + k];
        #pragma unroll
        for (int m = 0; m < 3; ++m) {
            float4 bv = *(const float4*)(sB0 + m * 4096 + k * 64);
            #pragma unroll
            for (int i = 0; i < 4; ++i) {
                acc[m][i][0] += a[i] * bv.x; acc[m][i][1] += a[i] * bv.y;
                acc[m][i][2] += a[i] * bv.z; acc[m][i][3] += a[i] * bv.w;
            }
        }
    }
    #pragma unroll
    for (int m = 0; m < 3; ++m)
        #pragma unroll
        for (int i = 0; i < 4; ++i) {
            int row = rowBase + ty + 16 * i;
            if (row < NN)
                *(float4*)(d_C + (size_t)row * 1024 + 256 + m * 256 + h * 64 + c0) =
                    make_float4(acc[m][i][0], acc[m][i][1], acc[m][i][2], acc[m][i][3]);
        }
}
#define G2_SMEM ((3 * 4096 + 64 * HST) * (int)sizeof(float))

// ---------------- score kernel: TWO EDGES PER WARP, writes EDGE-order d_sc ----------
__global__ void score_kernel(const float* __restrict__ pos, const int* __restrict__ srcA,
                             const int* __restrict__ dstA, const int* __restrict__ interA,
                             const float* __restrict__ ao, const float* __restrict__ bnds) {
    int gw = (blockIdx.x * blockDim.x + threadIdx.x) >> 5;
    int lane = threadIdx.x & 31;
    int half = lane >> 4;
    int hl = lane & 15;
    int e = gw * 2 + half;
    if (e >= EE) return;

    int s = __ldg(srcA + e);
    int v = __ldg(dstA + e);
    int4 itv = __ldg((const int4*)interA + e);

    int j = min(hl, 8);
    int aid = (j >= 5) ? s : v;
    int k = (j >= 5) ? (j - 5) : (j - 1);
    int bid = s;
    if (j >= 1) {
        bid = (k == 0) ? itv.x : ((k == 1) ? itv.y : ((k == 2) ? itv.z : itv.w));
    }
    float ax = __ldg(pos + (size_t)aid * 3 + 0);
    float ay = __ldg(pos + (size_t)aid * 3 + 1);
    float az = __ldg(pos + (size_t)aid * 3 + 2);
    float bxp = __ldg(pos + (size_t)bid * 3 + 0);
    float byp = __ldg(pos + (size_t)bid * 3 + 1);
    float bzp = __ldg(pos + (size_t)bid * 3 + 2);
    float dd = sqrtf((ax - bxp) * (ax - bxp) + (ay - byp) * (ay - byp) + (az - bzp) * (az - bzp));
    int bkt = bucket(dd, bnds);

    int sb = half << 4;
    int i1   = __shfl_sync(0xffffffffu, bkt, sb + 0);
    int i2_0 = __shfl_sync(0xffffffffu, bkt, sb + 1);
    int i2_1 = __shfl_sync(0xffffffffu, bkt, sb + 2);
    int i2_2 = __shfl_sync(0xffffffffu, bkt, sb + 3);
    int i2_3 = __shfl_sync(0xffffffffu, bkt, sb + 4);
    int i3_0 = __shfl_sync(0xffffffffu, bkt, sb + 5);
    int i3_1 = __shfl_sync(0xffffffffu, bkt, sb + 6);
    int i3_2 = __shfl_sync(0xffffffffu, bkt, sb + 7);
    int i3_3 = __shfl_sync(0xffffffffu, bkt, sb + 8);

    const float* Cs = d_C + (size_t)s * 1024;
    const float* Cv = d_C + (size_t)v * 1024;

    float acc0, acc1, acc2, acc3;
    #define HEAD_SCORE(h, ITN, I2, I3, ACC) {                                               \
        const float* Ci = d_C + (size_t)(ITN) * 1024;                                        \
        float4 q1 = __ldg((const float4*)(Cs + 256 + (h) * 64) + hl);                        \
        float4 q2 = __ldg((const float4*)(Ci + 512 + (h) * 64) + hl);                        \
        float4 q3 = __ldg((const float4*)(Cv + 768 + (h) * 64) + hl);                        \
        float4 t1 = __ldg((const float4*)(d_T + ((0 * HH + (h)) * 32 + i1) * 64) + hl);      \
        float4 t2 = __ldg((const float4*)(d_T + ((1 * HH + (h)) * 32 + (I2)) * 64) + hl);    \
        float4 t3 = __ldg((const float4*)(d_T + ((2 * HH + (h)) * 32 + (I3)) * 64) + hl);    \
        float4 av = __ldg((const float4*)(ao + (h) * 64) + hl);                              \
        float z0 = q1.x + q2.x + q3.x + t1.x + t2.x + t3.x;                                  \
        float z1 = q1.y + q2.y + q3.y + t1.y + t2.y + t3.y;                                  \
        float z2 = q1.z + q2.z + q3.z + t1.z + t2.z + t3.z;                                  \
        float z3 = q1.w + q2.w + q3.w + t1.w + t2.w + t3.w;                                  \
        ACC = fast_tanh(z0) * av.x + fast_tanh(z1) * av.y                                    \
            + fast_tanh(z2) * av.z + fast_tanh(z3) * av.w;                                   \
    }
    HEAD_SCORE(0, itv.x, i2_0, i3_0, acc0)
    HEAD_SCORE(1, itv.y, i2_1, i3_1, acc1)
    HEAD_SCORE(2, itv.z, i2_2, i3_2, acc2)
    HEAD_SCORE(3, itv.w, i2_3, i3_3, acc3)
    #undef HEAD_SCORE

    #pragma unroll
    for (int o = 8; o > 0; o >>= 1) {
        acc0 += __shfl_xor_sync(0xffffffffu, acc0, o);
        acc1 += __shfl_xor_sync(0xffffffffu, acc1, o);
        acc2 += __shfl_xor_sync(0xffffffffu, acc2, o);
        acc3 += __shfl_xor_sync(0xffffffffu, acc3, o);
    }
    if (hl == 0)
        *(float4*)(d_sc + (size_t)e * HH) = make_float4(acc0, acc1, acc2, acc3);
}

// ---------------- aggregation: two-pass softmax (exact segment max first) ----------
__global__ void agg_kernel(float* __restrict__ out) {
    int v = blockIdx.x;
    int tid = threadIdx.x;
    int h = tid >> 5, lane = tid & 31;
    __shared__ float sFT[4][64];

    int beg = d_off[v], end = d_off[v + 1];

    // pass 1: segment max (warp-parallel over edges, no serial chain)
    float mx = -3.4e38f;
    for (int c = beg + lane; c < end; c += 32)
        mx = fmaxf(mx, __ldg(d_sc + (size_t)__ldg(d_es + c) * HH + h));
    #pragma unroll
    for (int o = 16; o > 0; o >>= 1)
        mx = fmaxf(mx, __shfl_xor_sync(0xffffffffu, mx, o));

    // pass 2: independent weighted accumulation
    float den = 0.f, accx = 0.f, accy = 0.f;
    for (int c = beg; c < end; c += 32) {
        int n = min(32, end - c);
        int sL = 0; float wL = 0.f;
        if (lane < n) {
            int eL = __ldg(d_es + c + lane);
            sL = __ldg(d_srcs + c + lane);
            wL = __expf(__ldg(d_sc + (size_t)eL * HH + h) - mx);
        }
        for (int jj = 0; jj < n; ++jj) {
            int s   = __shfl_sync(0xffffffffu, sL, jj);
            float w = __shfl_sync(0xffffffffu, wL, jj);
            float2 hs = ((const float2*)(d_C + (size_t)s * 1024 + h * 64))[lane];
            den  += w;
            accx += w * hs.x;
            accy += w * hs.y;
        }
    }

    float inv = (den > 0.f) ? 1.0f / den : 0.f;
    sFT[h][lane * 2 + 0] = accx * inv;
    sFT[h][lane * 2 + 1] = accy * inv;
    __syncthreads();
    if (tid < 64)
        out[(size_t)v * 64 + tid] = 0.25f * (sFT[0][tid] + sFT[1][tid] + sFT[2][tid] + sFT[3][tid]);
}

// ---------------- launch ----------------
extern "C" void kernel_launch(void* const* d_in, const int* in_sizes, int n_in,
                              void* d_out, int out_size) {
    int i_feat = 0, i_loc = 1, i_src, i_dst, i_inter, i_wfc, i_emb, i_G,
        i_fc1, i_fc2, i_fc3, i_fc, i_ao, i_b;
    if (in_sizes[2] == EE) { // dict order
        i_src = 2; i_dst = 3; i_inter = 4; i_wfc = 5; i_emb = 6; i_G = 7;
        i_fc1 = 8; i_fc2 = 9; i_fc3 = 10; i_fc = 11; i_ao = 12; i_b = 13;
    } else {                 // signature order
        i_wfc = 2; i_emb = 3; i_G = 4; i_fc1 = 5; i_fc2 = 6; i_fc3 = 7;
        i_fc = 8; i_ao = 9; i_b = 10; i_src = 11; i_dst = 12; i_inter = 13;
    }

    const float* feat  = (const float*)d_in[i_feat];
    const float* pos   = (const float*)d_in[i_loc];
    const int*   src   = (const int*)  d_in[i_src];
    const int*   dst   = (const int*)  d_in[i_dst];
    const int*   inter = (const int*)  d_in[i_inter];
    const float* wfc   = (const float*)d_in[i_wfc];
    const float* emb   = (const float*)d_in[i_emb];
    const float* G     = (const float*)d_in[i_G];
    const float* fc1   = (const float*)d_in[i_fc1];
    const float* fc2   = (const float*)d_in[i_fc2];
    const float* fc3   = (const float*)d_in[i_fc3];
    const float* fcF   = (const float*)d_in[i_fc];
    const float* ao    = (const float*)d_in[i_ao];
    const float* bnds  = (const float*)d_in[i_b];
    float* out = (float*)d_out;

    cudaFuncSetAttribute(gemm2_kernel, cudaFuncAttributeMaxDynamicSharedMemorySize, G2_SMEM);

    // score is the 4th launch -> lands in the ncu capture slot this round
    prep_kernel<<<12, 256>>>(fc1, fc2, fc3, fcF, G, emb);
    gemm1_kernel<<<dim3(2, (NN + 127) / 128), 256>>>(feat, wfc);
    gemm2_kernel<<<dim3((NN + 63) / 64, 4), 256, G2_SMEM>>>();
    score_kernel<<<(EE / 2 + 7) / 8, 256>>>(pos, src, dst, inter, ao, bnds);
    zero_deg_kernel<<<(NN + 256) / 256, 256>>>();
    hist_kernel<<<(EE + 255) / 256, 256>>>(dst);
    scan_kernel<<<1, 1024>>>();
    scatter_kernel<<<(EE + 255) / 256, 256>>>(dst, src);
    agg_kernel<<<NN, 128>>>(out);
}